// round 2
// baseline (speedup 1.0000x reference)
#include <cuda_runtime.h>

// Problem constants (fixed by the reference)
#define NB   32        // batch
#define ND   1024      // input dim
#define NH   1024      // hidden dim
#define BETA 0.9f

// Closed forms:
//   u_new = BETA*u + x@w + b        [B,H]
//   out   = tanh(u_new)             [B,H]
//   E_w'  = BETA*E_w + x[b,d]       [1,B,D,H]
//   E_b'  = BETA*E_b + 1            [1,B,H]

#define TPB      256
#define NB_GEMM  64                       // blocks doing GEMM+epilogue
#define GRID     (148 * 8)                // one wave on 148 SMs
#define NSTREAM  (GRID - NB_GEMM)         // 1120 E_w streaming blocks
#define WARPS_PER_BLOCK (TPB / 32)
#define NSWARPS  (NSTREAM * WARPS_PER_BLOCK)   // 8960 streaming warps
#define NROWS    (NB * ND)                // 32768 rows of E_w, each 256 float4
#define VPR      (NH / 4)                 // 256 float4 per row
#define PHASES   (VPR / 32)               // 8 phases per lane

__global__ __launch_bounds__(TPB, 8)
void diag_rtrl_fused(const float* __restrict__ x,
                     const float* __restrict__ w,
                     const float* __restrict__ bias,
                     const float* __restrict__ u,
                     const float* __restrict__ Ew,
                     const float* __restrict__ Eb,
                     float* __restrict__ out)
{
    const int BH = NB * NH;
    float* o_out = out;                         // [B,H]
    float* o_u   = out + BH;                    // [B,H]
    float* o_Ew  = out + 2 * BH;                // [B,D,H]
    float* o_Eb  = out + 2 * BH + NB * ND * NH; // [B,H]

    if (blockIdx.x >= NB_GEMM) {
        // ---- E_w streaming: one (b,d) row per warp, MLP=8 ----
        const int swid = (blockIdx.x - NB_GEMM) * WARPS_PER_BLOCK + (threadIdx.x >> 5);
        const int lane = threadIdx.x & 31;

        const float4* __restrict__ Ew4 = (const float4*)Ew;
        float4*       __restrict__ O4  = (float4*)o_Ew;

        for (int row = swid; row < NROWS; row += NSWARPS) {
            const float xv = __ldg(&x[row]);           // uniform per warp
            const long long base = (long long)row * VPR + lane;

            float4 e[PHASES];
            #pragma unroll
            for (int p = 0; p < PHASES; p++)           // 8 loads in flight
                e[p] = __ldcs(&Ew4[base + p * 32]);

            #pragma unroll
            for (int p = 0; p < PHASES; p++) {
                float4 r;
                r.x = fmaf(BETA, e[p].x, xv);
                r.y = fmaf(BETA, e[p].y, xv);
                r.z = fmaf(BETA, e[p].z, xv);
                r.w = fmaf(BETA, e[p].w, xv);
                __stcs(&O4[base + p * 32], r);
            }
        }
    } else {
        // ---- GEMM + u_new + out + E_b ----
        // 16 b-groups (2 rows each) x 4 h-tiles (256 cols each) = 64 blocks
        __shared__ float xs[2][ND];                    // 8 KB
        const int bg = blockIdx.x >> 2;                // 0..15
        const int ht = blockIdx.x & 3;                 // 0..3
        const int b0 = bg * 2;
        const int tid = threadIdx.x;

        #pragma unroll
        for (int j = 0; j < 2; j++)
            for (int d = tid; d < ND; d += TPB)
                xs[j][d] = x[(b0 + j) * ND + d];
        __syncthreads();

        const int h = ht * TPB + tid;                  // coalesced over w cols
        float acc0 = 0.f, acc1 = 0.f;
        #pragma unroll 8
        for (int d = 0; d < ND; d++) {
            float wv = w[d * NH + h];
            acc0 = fmaf(xs[0][d], wv, acc0);
            acc1 = fmaf(xs[1][d], wv, acc1);
        }
        const float bv = bias[h];

        {
            const int i0 = (b0 + 0) * NH + h;
            float un = fmaf(BETA, u[i0], acc0 + bv);
            o_u[i0]   = un;
            o_out[i0] = tanhf(un);
            o_Eb[i0]  = fmaf(BETA, Eb[i0], 1.0f);
        }
        {
            const int i1 = (b0 + 1) * NH + h;
            float un = fmaf(BETA, u[i1], acc1 + bv);
            o_u[i1]   = un;
            o_out[i1] = tanhf(un);
            o_Eb[i1]  = fmaf(BETA, Eb[i1], 1.0f);
        }
    }
}

extern "C" void kernel_launch(void* const* d_in, const int* in_sizes, int n_in,
                              void* d_out, int out_size)
{
    const float* x   = (const float*)d_in[0];  // [32,1024]
    const float* w   = (const float*)d_in[1];  // [1024,1024]
    const float* b   = (const float*)d_in[2];  // [1024]
    const float* u   = (const float*)d_in[3];  // [32,1024]
    const float* Ew  = (const float*)d_in[4];  // [1,32,1024,1024]
    const float* Eb  = (const float*)d_in[5];  // [1,32,1024]
    float* out = (float*)d_out;

    diag_rtrl_fused<<<GRID, TPB>>>(x, w, b, u, Ew, Eb, out);
}